// round 3
// baseline (speedup 1.0000x reference)
#include <cuda_runtime.h>
#include <cuda_bf16.h>

#define EPS       0.1f
#define NTHREADS  256
#define BATCH     8
#define NEG_LOG2E -1.4426950408889634f

// Degree-4 poly for ln(1+t), t in [0,1] (max abs err ~2e-4). Constant term B0
// hoisted out and applied once per row.
#define PB0 2.012e-4f
#define PB1 0.9952132f
#define PB2 -0.4638212f
#define PB3 0.2162784f
#define PB4 -0.0548696f

typedef unsigned long long u64;

__device__ __forceinline__ float ex2f(float x) {
    float r; asm("ex2.approx.f32 %0, %1;" : "=f"(r) : "f"(x)); return r;
}
__device__ __forceinline__ u64 pk2(float lo, float hi) {
    u64 r; asm("mov.b64 %0, {%1, %2};" : "=l"(r) : "f"(lo), "f"(hi)); return r;
}
__device__ __forceinline__ u64 fma2(u64 a, u64 b, u64 c) {
    u64 d; asm("fma.rn.f32x2 %0, %1, %2, %3;" : "=l"(d) : "l"(a), "l"(b), "l"(c)); return d;
}
__device__ __forceinline__ float2 up2(u64 v) {
    float lo, hi; asm("mov.b64 {%0, %1}, %2;" : "=f"(lo), "=f"(hi) : "l"(v));
    return make_float2(lo, hi);
}

// Intrinsic-precision log-sigmoid for the ~100 sparse correction terms.
__device__ __forceinline__ float logsig_exact(float x) {
    float e = __expf(-fabsf(x));
    return fminf(x, 0.0f) - __logf(1.0f + e);
}

__global__ __launch_bounds__(NTHREADS, 4) void ls_loss_kernel(
    const float* __restrict__ output,
    const int*   __restrict__ label,
    const int*   __restrict__ test_label,
    float*       __restrict__ out,
    int num_type, int L)
{
    const int b    = blockIdx.x;
    const int tid  = threadIdx.x;
    const int twoL = 2 * L;

    __shared__ int   lab[128];
    __shared__ float warpsum[NTHREADS / 32];

    if (tid < L)         lab[tid] = label[b * L + tid];
    else if (tid < twoL) lab[tid] = test_label[b * L + (tid - L)];
    __syncthreads();

    const float  c0  = EPS / (float)num_type;
    const float* row = output + (size_t)b * (size_t)num_type;

    // ---- sparse prologue: resolve set semantics, ISSUE gathers early so the
    //      DRAM latency hides under the dense loop. Branchless fold later. ----
    float sp_w = 0.0f, sp_x = 0.0f;
    if (tid < twoL) {
        int raw = lab[tid];
        if (raw != 0) {
            bool canon = true;
            if (tid >= L) {
                for (int k = L; k < tid; k++)
                    if (lab[k] == raw) { canon = false; break; }
                if (canon) sp_w = 2.0f * (1.0f - EPS) - 2.0f * c0;
            } else {
                for (int k = 0; k < tid; k++)
                    if (lab[k] == raw) { canon = false; break; }
                if (canon)
                    for (int k = L; k < twoL; k++)
                        if (lab[k] == raw) { canon = false; break; }
                if (canon) sp_w = (1.0f - EPS) - c0;
            }
            if (sp_w != 0.0f) sp_x = __ldg(row + (raw - 1));  // in-flight during dense loop
        }
    }

    // packed poly constants
    const u64 B4p = pk2(PB4, PB4);
    const u64 B3p = pk2(PB3, PB3);
    const u64 B2p = pk2(PB2, PB2);
    const u64 B1p = pk2(PB1, PB1);

    // ---- dense: 8-deep explicitly batched float4 loads (MLP=8 per warp) ----
    float sm0 = 0.0f, sm1 = 0.0f;   // sum of min(x,0)
    u64 G0 = 0ull, G1 = 0ull;       // packed sums of t*Q(t)

    const int     nvec = num_type >> 2;          // float4 count (8000)
    const float4* rowv = (const float4*)row;
    const int     span = NTHREADS * BATCH;       // 2048 float4 per batched iter

    int base = 0;
    for (; base + span <= nvec; base += span) {
        float4 v[BATCH];
        #pragma unroll
        for (int k = 0; k < BATCH; k++)
            v[k] = __ldg(rowv + base + k * NTHREADS + tid);

        #pragma unroll
        for (int k = 0; k < BATCH; k++) {
            float t0 = ex2f(fabsf(v[k].x) * NEG_LOG2E);
            float t1 = ex2f(fabsf(v[k].y) * NEG_LOG2E);
            float t2 = ex2f(fabsf(v[k].z) * NEG_LOG2E);
            float t3 = ex2f(fabsf(v[k].w) * NEG_LOG2E);

            sm0 += fminf(v[k].x, 0.0f) + fminf(v[k].y, 0.0f);
            sm1 += fminf(v[k].z, 0.0f) + fminf(v[k].w, 0.0f);

            u64 ta = pk2(t0, t1);
            u64 tb = pk2(t2, t3);

            u64 p = fma2(ta, B4p, B3p);
            p     = fma2(ta, p,   B2p);
            p     = fma2(ta, p,   B1p);
            G0    = fma2(ta, p,   G0);

            u64 q = fma2(tb, B4p, B3p);
            q     = fma2(tb, q,   B2p);
            q     = fma2(tb, q,   B1p);
            G1    = fma2(tb, q,   G1);
        }
    }
    // remainder float4s (1856 here): simple strided loop, same poly math
    for (int i = base + tid; i < nvec; i += NTHREADS) {
        float4 v = __ldg(rowv + i);
        float t0 = ex2f(fabsf(v.x) * NEG_LOG2E);
        float t1 = ex2f(fabsf(v.y) * NEG_LOG2E);
        float t2 = ex2f(fabsf(v.z) * NEG_LOG2E);
        float t3 = ex2f(fabsf(v.w) * NEG_LOG2E);
        sm0 += fminf(v.x, 0.0f) + fminf(v.y, 0.0f);
        sm1 += fminf(v.z, 0.0f) + fminf(v.w, 0.0f);
        u64 ta = pk2(t0, t1);
        u64 tb = pk2(t2, t3);
        u64 p = fma2(ta, B4p, B3p);
        p     = fma2(ta, p,   B2p);
        p     = fma2(ta, p,   B1p);
        G0    = fma2(ta, p,   G0);
        u64 q = fma2(tb, B4p, B3p);
        q     = fma2(tb, q,   B2p);
        q     = fma2(tb, q,   B1p);
        G1    = fma2(tb, q,   G1);
    }
    // scalar tail (num_type % 4; empty for this shape)
    for (int i = (nvec << 2) + tid; i < num_type; i += NTHREADS)
        sm0 += logsig_exact(row[i]);

    float2 g0 = up2(G0), g1 = up2(G1);
    float  gsum = (g0.x + g0.y) + (g1.x + g1.y);
    float  acc  = ((sm0 + sm1) - gsum) * c0;

    // fold sparse correction (weight 0 kills inactive lanes)
    acc += sp_w * logsig_exact(sp_x);

    // ---- block reduction ----
    #pragma unroll
    for (int o = 16; o > 0; o >>= 1)
        acc += __shfl_down_sync(0xffffffffu, acc, o);
    if ((tid & 31) == 0) warpsum[tid >> 5] = acc;
    __syncthreads();

    if (tid < NTHREADS / 32) {
        float v = warpsum[tid];
        #pragma unroll
        for (int o = NTHREADS / 64; o > 0; o >>= 1)
            v += __shfl_down_sync(0xffu, v, o);
        if (tid == 0) {
            float corr = c0 * (float)(nvec << 2) * PB0;  // hoisted poly constant
            out[b] = corr - v;
        }
    }
}

extern "C" void kernel_launch(void* const* d_in, const int* in_sizes, int n_in,
                              void* d_out, int out_size)
{
    const float* output     = (const float*)d_in[0];
    const int*   label      = (const int*)d_in[1];
    const int*   test_label = (const int*)d_in[2];
    float*       out        = (float*)d_out;

    const int B        = out_size;               // 4096
    const int num_type = in_sizes[0] / B;        // 32000
    const int L        = in_sizes[1] / B;        // 50

    ls_loss_kernel<<<B, NTHREADS>>>(output, label, test_label, out, num_type, L);
}

// round 4
// speedup vs baseline: 1.2176x; 1.2176x over previous
#include <cuda_runtime.h>
#include <cuda_bf16.h>
#include <cstdint>

#define EPS        0.1f
#define NTHREADS   256
#define NSTAGES    4
#define TILE_BYTES 8000              // 2000 floats / 500 float4 per tile, %16==0
#define TILE_F4    (TILE_BYTES / 16)
#define NEG_LOG2E  -1.4426950408889634f

// Degree-4 poly for ln(1+t), t in [0,1] (max abs err ~2e-4). B0 hoisted out.
#define PB0 2.012e-4f
#define PB1 0.9952132f
#define PB2 -0.4638212f
#define PB3 0.2162784f
#define PB4 -0.0548696f

typedef unsigned long long u64;

__device__ __forceinline__ float ex2f(float x) {
    float r; asm("ex2.approx.f32 %0, %1;" : "=f"(r) : "f"(x)); return r;
}
__device__ __forceinline__ u64 pk2(float lo, float hi) {
    u64 r; asm("mov.b64 %0, {%1, %2};" : "=l"(r) : "f"(lo), "f"(hi)); return r;
}
__device__ __forceinline__ u64 fma2(u64 a, u64 b, u64 c) {
    u64 d; asm("fma.rn.f32x2 %0, %1, %2, %3;" : "=l"(d) : "l"(a), "l"(b), "l"(c)); return d;
}
__device__ __forceinline__ float2 up2(u64 v) {
    float lo, hi; asm("mov.b64 {%0, %1}, %2;" : "=f"(lo), "=f"(hi) : "l"(v));
    return make_float2(lo, hi);
}
__device__ __forceinline__ uint32_t smem_u32(const void* p) {
    uint32_t a;
    asm("{ .reg .u64 t; cvta.to.shared.u64 t, %1; cvt.u32.u64 %0, t; }" : "=r"(a) : "l"(p));
    return a;
}
__device__ __forceinline__ void mbar_init(uint32_t mbar, uint32_t cnt) {
    asm volatile("mbarrier.init.shared.b64 [%0], %1;" :: "r"(mbar), "r"(cnt) : "memory");
}
__device__ __forceinline__ void mbar_expect_tx(uint32_t mbar, uint32_t bytes) {
    asm volatile("mbarrier.arrive.expect_tx.shared.b64 _, [%0], %1;"
                 :: "r"(mbar), "r"(bytes) : "memory");
}
__device__ __forceinline__ void bulk_g2s(uint32_t dst, const void* src,
                                         uint32_t bytes, uint32_t mbar) {
    asm volatile(
        "cp.async.bulk.shared::cluster.global.mbarrier::complete_tx::bytes "
        "[%0], [%1], %2, [%3];"
        :: "r"(dst), "l"(src), "r"(bytes), "r"(mbar) : "memory");
}
__device__ __forceinline__ void mbar_wait(uint32_t mbar, uint32_t parity) {
    uint32_t done;
    asm volatile(
        "{\n\t.reg .pred p;\n\t"
        "mbarrier.try_wait.parity.acquire.cta.shared::cta.b64 p, [%1], %2;\n\t"
        "selp.b32 %0, 1, 0, p;\n\t}"
        : "=r"(done) : "r"(mbar), "r"(parity) : "memory");
    if (!done) {
        asm volatile(
            "{\n\t.reg .pred P1;\n\t"
            "W_%=:\n\t"
            "mbarrier.try_wait.parity.acquire.cta.shared::cta.b64 P1, [%0], %1, 0x989680;\n\t"
            "@P1 bra.uni D_%=;\n\t"
            "bra.uni W_%=;\n\t"
            "D_%=:\n\t}"
            :: "r"(mbar), "r"(parity) : "memory");
    }
}

// Intrinsic-precision log-sigmoid for sparse correction terms.
__device__ __forceinline__ float logsig_exact(float x) {
    float e = __expf(-fabsf(x));
    return fminf(x, 0.0f) - __logf(1.0f + e);
}

__global__ __launch_bounds__(NTHREADS) void ls_loss_kernel(
    const float* __restrict__ output,
    const int*   __restrict__ label,
    const int*   __restrict__ test_label,
    float*       __restrict__ out,
    int num_type, int L)
{
    __shared__ __align__(16) float tiles[NSTAGES][TILE_BYTES / 4];
    __shared__ __align__(8)  u64   mbar[NSTAGES];
    __shared__ int   lab[128];
    __shared__ float warpsum[NTHREADS / 32];

    const int b    = blockIdx.x;
    const int tid  = threadIdx.x;
    const int twoL = 2 * L;

    if (tid < L)         lab[tid] = label[b * L + tid];
    else if (tid < twoL) lab[tid] = test_label[b * L + (tid - L)];

    const uint32_t mbar0 = smem_u32(&mbar[0]);
    if (tid == 0) {
        #pragma unroll
        for (int s = 0; s < NSTAGES; s++) mbar_init(mbar0 + 8 * s, 1);
    }
    __syncthreads();

    const float  c0  = EPS / (float)num_type;
    const float* row = output + (size_t)b * (size_t)num_type;

    // bulk-copied region: nvec4 float4 = bulk_bytes (multiple of 16 when num_type%4==0)
    const int nvec4      = num_type >> 2;
    const int bulk_bytes = nvec4 * 16;
    const int ntiles     = (bulk_bytes + TILE_BYTES - 1) / TILE_BYTES;
    const int last_bytes = bulk_bytes - (ntiles - 1) * TILE_BYTES;

    const uint32_t tiles0 = smem_u32(&tiles[0][0]);

    // ---- kick off the pipeline ----
    if (tid == 0) {
        #pragma unroll
        for (int s = 0; s < NSTAGES; s++) {
            if (s < ntiles) {
                uint32_t sz = (s == ntiles - 1) ? (uint32_t)last_bytes : (uint32_t)TILE_BYTES;
                mbar_expect_tx(mbar0 + 8 * s, sz);
                bulk_g2s(tiles0 + s * TILE_BYTES,
                         (const char*)row + (size_t)s * TILE_BYTES, sz, mbar0 + 8 * s);
            }
        }
    }

    // ---- sparse resolution + early gather (latency hides under dense loop) ----
    float sp_w = 0.0f, sp_x = 0.0f;
    if (tid < twoL) {
        int raw = lab[tid];
        if (raw != 0) {
            bool canon = true;
            if (tid >= L) {
                for (int k = L; k < tid; k++)
                    if (lab[k] == raw) { canon = false; break; }
                if (canon) sp_w = 2.0f * (1.0f - EPS) - 2.0f * c0;
            } else {
                for (int k = 0; k < tid; k++)
                    if (lab[k] == raw) { canon = false; break; }
                if (canon)
                    for (int k = L; k < twoL; k++)
                        if (lab[k] == raw) { canon = false; break; }
                if (canon) sp_w = (1.0f - EPS) - c0;
            }
            if (sp_w != 0.0f) sp_x = __ldg(row + (raw - 1));
        }
    }

    // packed poly constants
    const u64 B4p = pk2(PB4, PB4);
    const u64 B3p = pk2(PB3, PB3);
    const u64 B2p = pk2(PB2, PB2);
    const u64 B1p = pk2(PB1, PB1);

    float sm0 = 0.0f, sm1 = 0.0f;   // sum of min(x,0)
    u64 G0 = 0ull, G1 = 0ull;       // packed sums of t*Q(t)

    // ---- dense mainloop: consume staged tiles from smem ----
    for (int t = 0; t < ntiles; t++) {
        const int      stage  = t & (NSTAGES - 1);
        const uint32_t parity = (t >> 2) & 1;
        mbar_wait(mbar0 + 8 * stage, parity);

        const int f4cnt = ((t == ntiles - 1) ? last_bytes : TILE_BYTES) >> 4;
        const float4* tp = (const float4*)&tiles[stage][0];

        for (int i = tid; i < f4cnt; i += NTHREADS) {
            float4 v = tp[i];
            float t0 = ex2f(fabsf(v.x) * NEG_LOG2E);
            float t1 = ex2f(fabsf(v.y) * NEG_LOG2E);
            float t2 = ex2f(fabsf(v.z) * NEG_LOG2E);
            float t3 = ex2f(fabsf(v.w) * NEG_LOG2E);

            sm0 += fminf(v.x, 0.0f) + fminf(v.y, 0.0f);
            sm1 += fminf(v.z, 0.0f) + fminf(v.w, 0.0f);

            u64 ta = pk2(t0, t1);
            u64 tb = pk2(t2, t3);

            u64 p = fma2(ta, B4p, B3p);
            p     = fma2(ta, p,   B2p);
            p     = fma2(ta, p,   B1p);
            G0    = fma2(ta, p,   G0);

            u64 q = fma2(tb, B4p, B3p);
            q     = fma2(tb, q,   B2p);
            q     = fma2(tb, q,   B1p);
            G1    = fma2(tb, q,   G1);
        }

        __syncthreads();  // all readers done with this buffer before refill

        const int nt = t + NSTAGES;
        if (tid == 0 && nt < ntiles) {
            uint32_t sz = (nt == ntiles - 1) ? (uint32_t)last_bytes : (uint32_t)TILE_BYTES;
            mbar_expect_tx(mbar0 + 8 * stage, sz);
            bulk_g2s(tiles0 + stage * TILE_BYTES,
                     (const char*)row + (size_t)nt * TILE_BYTES, sz, mbar0 + 8 * stage);
        }
    }

    // scalar tail (num_type % 4; empty for this shape)
    for (int i = (nvec4 << 2) + tid; i < num_type; i += NTHREADS)
        sm0 += logsig_exact(row[i]);

    float2 g0 = up2(G0), g1 = up2(G1);
    float  gsum = (g0.x + g0.y) + (g1.x + g1.y);
    float  acc  = ((sm0 + sm1) - gsum) * c0;

    acc += sp_w * logsig_exact(sp_x);   // weight 0 kills inactive lanes

    // ---- block reduction ----
    #pragma unroll
    for (int o = 16; o > 0; o >>= 1)
        acc += __shfl_down_sync(0xffffffffu, acc, o);
    if ((tid & 31) == 0) warpsum[tid >> 5] = acc;
    __syncthreads();

    if (tid < NTHREADS / 32) {
        float v = warpsum[tid];
        #pragma unroll
        for (int o = NTHREADS / 64; o > 0; o >>= 1)
            v += __shfl_down_sync(0xffu, v, o);
        if (tid == 0) {
            float corr = c0 * (float)(nvec4 << 2) * PB0;  // hoisted poly constant
            out[b] = corr - v;
        }
    }
}

extern "C" void kernel_launch(void* const* d_in, const int* in_sizes, int n_in,
                              void* d_out, int out_size)
{
    const float* output     = (const float*)d_in[0];
    const int*   label      = (const int*)d_in[1];
    const int*   test_label = (const int*)d_in[2];
    float*       out        = (float*)d_out;

    const int B        = out_size;               // 4096
    const int num_type = in_sizes[0] / B;        // 32000
    const int L        = in_sizes[1] / B;        // 50

    ls_loss_kernel<<<B, NTHREADS>>>(output, label, test_label, out, num_type, L);
}